// round 9
// baseline (speedup 1.0000x reference)
#include <cuda_runtime.h>
#include <cuda_bf16.h>

#define NS 2048
#define CC 512
#define HW 49
#define EPS 1e-5f
#define ELEMS (CC * HW)            // 25088 floats per sample
#define VEC4 (ELEMS / 4)           // 6272 = 512*12 + 128

__global__ __launch_bounds__(512, 3)
void gate_twopass_kernel(const float* __restrict__ x, float* __restrict__ out) {
    __shared__ float y_s[CC];          // per-channel spatial means
    __shared__ float gate_s[CC + 4];   // padded: c+1 probe at c=511 stays in-bounds
    __shared__ float warp_a[16];
    __shared__ float warp_b[16];

    const int n   = blockIdx.x;
    const int tid = threadIdx.x;
    const int wid = tid >> 5;
    const int lid = tid & 31;

    const float* __restrict__ xs = x + (size_t)n * ELEMS;
    float*       __restrict__ os = out + (size_t)n * ELEMS;

    // ---- Pass 1: per-channel spatial mean, one warp per channel ----
    #pragma unroll 4
    for (int k = 0; k < CC / 16; k++) {
        const int c = k * 16 + wid;
        const float* __restrict__ row = xs + c * HW;
        float v = row[lid];
        if (lid < HW - 32) v += row[32 + lid];
        #pragma unroll
        for (int o = 16; o > 0; o >>= 1)
            v += __shfl_xor_sync(0xffffffffu, v, o);
        if (lid == 0) y_s[c] = v * (1.0f / (float)HW);
    }

    // ---- Prefetch first 4 pass-2 vectors: keeps DRAM/L2 busy across the
    //      stats barriers (loads are independent of the gates) ----
    const float4* __restrict__ x4 = (const float4*)xs;
    float4*       __restrict__ o4 = (float4*)os;
    float4 p0 = __ldcs(x4 + tid);
    float4 p1 = __ldcs(x4 + tid + 512);
    float4 p2 = __ldcs(x4 + tid + 1024);
    float4 p3 = __ldcs(x4 + tid + 1536);

    __syncthreads();

    // ---- Stats over y[512]: warp partials, then redundant final reduce ----
    const float y = y_s[tid];
    float sy = y, sy2 = y * y;
    #pragma unroll
    for (int o = 16; o > 0; o >>= 1) {
        sy  += __shfl_xor_sync(0xffffffffu, sy,  o);
        sy2 += __shfl_xor_sync(0xffffffffu, sy2, o);
    }
    if (lid == 0) { warp_a[wid] = sy; warp_b[wid] = sy2; }
    __syncthreads();

    // every thread reduces the 16 partials (broadcast LDS, no extra barrier)
    float a = 0.0f, b = 0.0f;
    #pragma unroll
    for (int j = 0; j < 16; j++) { a += warp_a[j]; b += warp_b[j]; }
    const float m   = a * (1.0f / (float)CC);
    const float mx2 = b * (1.0f / (float)CC);
    float var = mx2 - m * m;
    var = var > 0.0f ? var : 0.0f;
    const float inv = rsqrtf(var + EPS);
    const float yn  = (y - m) * inv;
    gate_s[tid] = __expf(-yn * yn);    // exp(-0.5 * C_PARAM * yn^2), C_PARAM = 2
    __syncthreads();

    // ---- Pass 2: gate + streaming store ----
    // Incremental channel tracking: e advances by 2048 = 41*49 + 39 per iter.
    unsigned i = (unsigned)tid;
    unsigned c = ((unsigned)tid * 4u) / 49u;
    unsigned r = (unsigned)tid * 4u - c * 49u;     // remainder in [0,48]

    // first 4 iterations consume the prefetched registers
    #pragma unroll
    for (int k = 0; k < 4; k++) {
        float4 v = (k == 0) ? p0 : (k == 1) ? p1 : (k == 2) ? p2 : p3;
        const float g0 = gate_s[c];
        const float g1 = gate_s[c + 1];
        v.x *= g0;                                 // r < 49 always
        v.y *= (r + 1u < 49u) ? g0 : g1;
        v.z *= (r + 2u < 49u) ? g0 : g1;
        v.w *= (r + 3u < 49u) ? g0 : g1;
        __stcs(o4 + i, v);
        i += 512u;
        c += 41u; r += 39u;
        if (r >= 49u) { r -= 49u; c += 1u; }
    }

    #pragma unroll 4
    for (int k = 4; k < 12; k++) {
        float4 v = __ldcs(x4 + i);
        const float g0 = gate_s[c];
        const float g1 = gate_s[c + 1];
        v.x *= g0;
        v.y *= (r + 1u < 49u) ? g0 : g1;
        v.z *= (r + 2u < 49u) ? g0 : g1;
        v.w *= (r + 3u < 49u) ? g0 : g1;
        __stcs(o4 + i, v);
        i += 512u;
        c += 41u; r += 39u;
        if (r >= 49u) { r -= 49u; c += 1u; }
    }

    // tail: first 128 threads handle float4s 6144..6271
    if (tid < 128) {
        const unsigned ii = (unsigned)tid + 6144u;
        const unsigned e  = ii * 4u;
        const unsigned ct = e / 49u;
        const unsigned rt = e - ct * 49u;
        float4 v = __ldcs(x4 + ii);
        const float g0 = gate_s[ct];
        const float g1 = gate_s[ct + 1];
        v.x *= g0;
        v.y *= (rt + 1u < 49u) ? g0 : g1;
        v.z *= (rt + 2u < 49u) ? g0 : g1;
        v.w *= (rt + 3u < 49u) ? g0 : g1;
        __stcs(o4 + ii, v);
    }
}

extern "C" void kernel_launch(void* const* d_in, const int* in_sizes, int n_in,
                              void* d_out, int out_size) {
    (void)in_sizes; (void)n_in; (void)out_size;
    const float* x = (const float*)d_in[0];
    float* out = (float*)d_out;
    gate_twopass_kernel<<<NS, 512>>>(x, out);
}